// round 10
// baseline (speedup 1.0000x reference)
#include <cuda_runtime.h>
#include <cuda_bf16.h>
#include <cstdint>

#define HH      200
#define NWARP   7
#define THREADS 224

// per-warp A staging: tile0 = 32 rows x 128B (SW128-swizzled bf16, k 0..63)
//                     tile1 = 32 rows x 32B  (k 64..79: dist, const-1, pad)
#define T0_BYTES (32 * 128)
#define T1_BYTES (32 * 32)
#define AW_BYTES (T0_BYTES + T1_BYTES)

// B matrix in mma fragment order: [kk=5][nn=4][r=2][lane=32] bf16x2 words.
// Word(kk,nn,r,l) = pack( B[k0+1][n], B[k0][n] ),
//   n = 8*nn + (l>>2),  k0 = 16*kk + 8*r + 2*(l&3)
//   B[k][n]: k<66 -> attn1_W[k][n], k==66 -> attn1_b[n], else 0.
__device__ __align__(16) uint32_t g_Bfrag[5 * 4 * 2 * 32];

__device__ __forceinline__ uint32_t cvt2bf(float hi, float lo) {
    uint32_t r;
    asm("cvt.rn.bf16x2.f32 %0, %1, %2;" : "=r"(r) : "f"(hi), "f"(lo));
    return r;
}
__device__ __forceinline__ float sigm(float x) {
    return __fdividef(1.f, 1.f + __expf(-x));
}
__device__ __forceinline__ void ldsm_x4(uint32_t addr, uint32_t& r0, uint32_t& r1,
                                        uint32_t& r2, uint32_t& r3) {
    asm volatile("ldmatrix.sync.aligned.m8n8.x4.shared.b16 {%0,%1,%2,%3}, [%4];"
                 : "=r"(r0), "=r"(r1), "=r"(r2), "=r"(r3) : "r"(addr));
}
__device__ __forceinline__ void mma16816(float* d, const uint32_t* a,
                                         uint32_t b0, uint32_t b1) {
    asm volatile(
        "mma.sync.aligned.m16n8k16.row.col.f32.bf16.bf16.f32 "
        "{%0,%1,%2,%3}, {%4,%5,%6,%7}, {%8,%9}, {%0,%1,%2,%3};"
        : "+f"(d[0]), "+f"(d[1]), "+f"(d[2]), "+f"(d[3])
        : "r"(a[0]), "r"(a[1]), "r"(a[2]), "r"(a[3]), "r"(b0), "r"(b1));
}

// ---- prologue: build fragment-order B (one tiny block) ---------------------
__global__ void build_Bfrag(const float* __restrict__ attn1_W,
                            const float* __restrict__ attn1_b) {
    for (int t = threadIdx.x; t < 5 * 4 * 2 * 32; t += blockDim.x) {
        int l   = t & 31;
        int r   = (t >> 5) & 1;
        int nn  = (t >> 6) & 3;
        int kk  = t >> 8;
        int n   = 8 * nn + (l >> 2);
        int k0  = 16 * kk + 8 * r + 2 * (l & 3);
        auto bval = [&](int k) -> float {
            if (k < 66)  return attn1_W[k * 32 + n];
            if (k == 66) return attn1_b[n];
            return 0.f;
        };
        g_Bfrag[t] = cvt2bf(bval(k0 + 1), bval(k0));
    }
}

// ---------------------------------------------------------------------------
// One block per batch row. 7 warps; warp w owns positions [32w, 32w+32).
// Warps fully independent until the final 56B reduction.
//
// Gather lane mapping: within each 8-lane row group, lane c owns dest 16B
// chunk c of the A row (c<4: hist-product k[8c..8c+8), c>=4: reg-product
// k[8c..8c+8)). Source = 32B contiguous fp32 (2 LDG.128, same 128B line),
// one STS.128 per q. dot(h,t) accumulated in fp32 via 8-lane butterfly.
//
// Swizzled dest for row prow = 4q+rsel, chunk c:
//   prow*128 + ((c ^ (prow&7)) << 4)
//     = 512q + 128*rsel + (((c ^ rsel) ^ 4*(q&1)) << 4)   [proper XOR!]
//
// MMA: D[32, 32] per warp = A[32, 80] x B[80, 32]  (bf16 in, fp32 acc)
// ---------------------------------------------------------------------------
__global__ __launch_bounds__(THREADS, 4)
void nais_kernel(const int*   __restrict__ history,
                 const int*   __restrict__ target,
                 const int*   __restrict__ history_region,
                 const int*   __restrict__ target_region,
                 const float* __restrict__ lat_long,
                 const float* __restrict__ W_hist,
                 const float* __restrict__ W_tgt,
                 const float* __restrict__ W_reg,
                 const float* __restrict__ attn2_W,
                 const float* __restrict__ dist_W,
                 const float* __restrict__ dist_b,
                 float*       __restrict__ out)
{
    __shared__ __align__(16) unsigned char s_A[NWARP * AW_BYTES];
    __shared__ float  s_dot[NWARP * 32];
    __shared__ float2 s_red[NWARP];

    const int b    = blockIdx.x;
    const int tid  = threadIdx.x;
    const int w    = tid >> 5;
    const int lane = tid & 31;
    const int gid  = lane >> 2;
    const int tig  = lane & 3;
    const int base = b * HH;
    const int tgt  = target[b];
    const int treg = target_region[b];
    const int tb   = 32 * w;
    const int c    = lane & 7;       // dest 16B chunk this lane owns
    const int cc   = c & 3;          // chunk within the half-table
    const int rsel = lane >> 3;      // row served within each 4-row group

    unsigned char* myA = s_A + w * AW_BYTES;

    // ---- this lane's target source chunk: 32B fp32 from its table half
    const float* tptr = (c < 4) ? (W_tgt + (size_t)tgt * 32 + 8 * cc)
                                : (W_reg + (size_t)treg * 32 + 8 * cc);
    const float4 t0 = *(const float4*)tptr;
    const float4 t1 = *(const float4*)(tptr + 4);

    // ---- tile1 init: row = lane. chunk0 = (dist placeholder, k66=1.0, 0, 0)
    {
        uint4* r = (uint4*)(myA + T0_BYTES + lane * 32);
        r[0] = make_uint4(0u, 0x00003F80u, 0u, 0u);
        r[1] = make_uint4(0u, 0u, 0u, 0u);
    }

    // ---- dist features -> tile1 word0 (same lane, program-ordered after init)
    {
        const int posl = min(tb + lane, HH - 1);
        float2 ll = *(const float2*)(lat_long + (size_t)(base + posl) * 2);
        const float dw00 = dist_W[0] * 100.f, dw01 = dist_W[1] * 100.f;
        const float dw10 = dist_W[2] * 100.f, dw11 = dist_W[3] * 100.f;
        float d0 = sigm(fmaf(ll.x, dw00, fmaf(ll.y, dw10, dist_b[0])));
        float d1 = sigm(fmaf(ll.x, dw01, fmaf(ll.y, dw11, dist_b[1])));
        *(uint32_t*)(myA + T0_BYTES + lane * 32) = cvt2bf(d1, d0);
    }

    // ---- gather + product + fp32 dot + cvt + one STS.128 per q
    {
        // even-q / odd-q swizzled base pointers (proper XOR, no carry)
        unsigned char* dstE = myA + 128 * rsel + (((c ^ rsel)    ) << 4);
        unsigned char* dstO = myA + 128 * rsel + (((c ^ rsel) ^ 4) << 4);
#pragma unroll
        for (int q = 0; q < 8; q++) {
            int prow = 4 * q + rsel;                 // local position 0..31
            int gpos = min(tb + prow, HH - 1);
            int ii = history[base + gpos];           // 8-lane broadcast load
            int rr = history_region[base + gpos];
            const float* eptr = (c < 4) ? (W_hist + (size_t)ii * 32 + 8 * cc)
                                        : (W_reg  + (size_t)rr * 32 + 8 * cc);
            float4 e0 = *(const float4*)eptr;
            float4 e1 = *(const float4*)(eptr + 4);
            float p0 = e0.x * t0.x, p1 = e0.y * t0.y;
            float p2 = e0.z * t0.z, p3 = e0.w * t0.w;
            float p4 = e1.x * t1.x, p5 = e1.y * t1.y;
            float p6 = e1.z * t1.z, p7 = e1.w * t1.w;
            uint4 v = make_uint4(cvt2bf(p1, p0), cvt2bf(p3, p2),
                                 cvt2bf(p5, p4), cvt2bf(p7, p6));
            unsigned char* dst = (q & 1) ? dstO : dstE;
            *(uint4*)(dst + 512 * q) = v;
            // fp32 dot over the 8 lanes sharing this row
            float part = ((p0 + p1) + (p2 + p3)) + ((p4 + p5) + (p6 + p7));
            part += __shfl_xor_sync(0xffffffffu, part, 1);
            part += __shfl_xor_sync(0xffffffffu, part, 2);
            part += __shfl_xor_sync(0xffffffffu, part, 4);
            if (c == 0) s_dot[w * 32 + prow] = part;
        }
    }
    __syncwarp();   // per-warp only: A tile + s_dot visible to this warp

    // ---- MMA: 2 m-tiles x 4 n-tiles x 5 k-steps; B frags via LDG
    float d[2][4][4];
#pragma unroll
    for (int mt = 0; mt < 2; mt++)
#pragma unroll
        for (int nn = 0; nn < 4; nn++)
#pragma unroll
            for (int i = 0; i < 4; i++) d[mt][nn][i] = 0.f;

    const uint32_t aT0 = (uint32_t)__cvta_generic_to_shared(myA);
    const uint32_t aT1 = aT0 + T0_BYTES;

#pragma unroll
    for (int kk = 0; kk < 5; kk++) {
        uint32_t a[2][4];
#pragma unroll
        for (int mt = 0; mt < 2; mt++) {
            int row = 16 * mt + (lane & 15);
            uint32_t addr;
            if (kk < 4) {
                int chunk = 2 * kk + (lane >> 4);
                addr = aT0 + row * 128 + ((chunk ^ (row & 7)) << 4);
            } else {
                addr = aT1 + row * 32 + ((lane >> 4) << 4);
            }
            ldsm_x4(addr, a[mt][0], a[mt][1], a[mt][2], a[mt][3]);
        }
#pragma unroll
        for (int nn = 0; nn < 4; nn++) {
            uint32_t b0 = g_Bfrag[((kk * 4 + nn) * 2    ) * 32 + lane];
            uint32_t b1 = g_Bfrag[((kk * 4 + nn) * 2 + 1) * 32 + lane];
            mma16816(d[0][nn], a[0], b0, b1);
            mma16816(d[1][nn], a[1], b0, b1);
        }
    }

    // ---- epilogue: relu(hid) . w2, masked exp, reduce
    float v00 = 0.f, v01 = 0.f, v10 = 0.f, v11 = 0.f;
#pragma unroll
    for (int nn = 0; nn < 4; nn++) {
        float2 w2 = *(const float2*)(attn2_W + 8 * nn + 2 * tig);
        v00 = fmaf(fmaxf(d[0][nn][0], 0.f), w2.x, fmaf(fmaxf(d[0][nn][1], 0.f), w2.y, v00));
        v01 = fmaf(fmaxf(d[0][nn][2], 0.f), w2.x, fmaf(fmaxf(d[0][nn][3], 0.f), w2.y, v01));
        v10 = fmaf(fmaxf(d[1][nn][0], 0.f), w2.x, fmaf(fmaxf(d[1][nn][1], 0.f), w2.y, v10));
        v11 = fmaf(fmaxf(d[1][nn][2], 0.f), w2.x, fmaf(fmaxf(d[1][nn][3], 0.f), w2.y, v11));
    }
#pragma unroll
    for (int off = 1; off <= 2; off <<= 1) {
        v00 += __shfl_xor_sync(0xffffffffu, v00, off);
        v01 += __shfl_xor_sync(0xffffffffu, v01, off);
        v10 += __shfl_xor_sync(0xffffffffu, v10, off);
        v11 += __shfl_xor_sync(0xffffffffu, v11, off);
    }
    float score = (tig == 0) ? v00 : (tig == 1) ? v01 : (tig == 2) ? v10 : v11;

    int posl2 = gid + 8 * tig;                       // local row this lane owns
    float dotv = s_dot[w * 32 + posl2];              // fp32 dot (conflict-free)
    int idx = history[base + min(tb + posl2, HH - 1)];
    bool ok = (idx != tgt) && (tb + posl2 < HH);
    float e  = ok ? __expf(score) : 0.f;
    float se = e;
    float sp = e * dotv;
#pragma unroll
    for (int off = 16; off; off >>= 1) {
        se += __shfl_xor_sync(0xffffffffu, se, off);
        sp += __shfl_xor_sync(0xffffffffu, sp, off);
    }
    if (lane == 0) s_red[w] = make_float2(se, sp);
    __syncthreads();
    if (tid == 0) {
        float SE = 0.f, SP = 0.f;
#pragma unroll
        for (int i = 0; i < NWARP; i++) { SE += s_red[i].x; SP += s_red[i].y; }
        out[b] = sigm(SP * rsqrtf(SE));   // BETA=0.5: pred = SP / sqrt(SE)
    }
}

extern "C" void kernel_launch(void* const* d_in, const int* in_sizes, int n_in,
                              void* d_out, int out_size) {
    const int B = in_sizes[1];   // target is [B]
    build_Bfrag<<<1, 256>>>((const float*)d_in[8], (const float*)d_in[9]);
    nais_kernel<<<B, THREADS>>>(
        (const int*)  d_in[0],   // history [B,H]
        (const int*)  d_in[1],   // target [B]
        (const int*)  d_in[2],   // history_region [B,H]
        (const int*)  d_in[3],   // target_region [B]
        (const float*)d_in[4],   // target_lat_long [B,H,2]
        (const float*)d_in[5],   // W_hist
        (const float*)d_in[6],   // W_tgt
        (const float*)d_in[7],   // W_reg
        (const float*)d_in[10],  // attn2_W [32,1]
        (const float*)d_in[11],  // dist_W [2,2]
        (const float*)d_in[12],  // dist_b [2]
        (float*)d_out);
}

// round 11
// speedup vs baseline: 1.1215x; 1.1215x over previous
#include <cuda_runtime.h>
#include <cuda_bf16.h>
#include <cstdint>

#define HH      200
#define NWARP   7
#define THREADS 224

// per-warp A staging: tile0 = 32 rows x 128B (SW128-swizzled bf16, k 0..63)
//                     tile1 = 32 rows x 32B  (k 64..79: dist, const-1, pad)
#define T0_BYTES (32 * 128)
#define T1_BYTES (32 * 32)
#define AW_BYTES (T0_BYTES + T1_BYTES)

// B matrix in mma fragment order: [kk=5][nn=4][r=2][lane=32] bf16x2 words.
// Word(kk,nn,r,l) = pack( B[k0+1][n], B[k0][n] ),
//   n = 8*nn + (l>>2),  k0 = 16*kk + 8*r + 2*(l&3)
//   B[k][n]: k<66 -> attn1_W[k][n], k==66 -> attn1_b[n], else 0.
__device__ __align__(16) uint32_t g_Bfrag[5 * 4 * 2 * 32];

__device__ __forceinline__ uint32_t cvt2bf(float hi, float lo) {
    uint32_t r;
    asm("cvt.rn.bf16x2.f32 %0, %1, %2;" : "=r"(r) : "f"(hi), "f"(lo));
    return r;
}
__device__ __forceinline__ float sigm(float x) {
    return __fdividef(1.f, 1.f + __expf(-x));
}
__device__ __forceinline__ void ldsm_x4(uint32_t addr, uint32_t& r0, uint32_t& r1,
                                        uint32_t& r2, uint32_t& r3) {
    asm volatile("ldmatrix.sync.aligned.m8n8.x4.shared.b16 {%0,%1,%2,%3}, [%4];"
                 : "=r"(r0), "=r"(r1), "=r"(r2), "=r"(r3) : "r"(addr));
}
__device__ __forceinline__ void mma16816(float* d, const uint32_t* a,
                                         uint32_t b0, uint32_t b1) {
    asm volatile(
        "mma.sync.aligned.m16n8k16.row.col.f32.bf16.bf16.f32 "
        "{%0,%1,%2,%3}, {%4,%5,%6,%7}, {%8,%9}, {%0,%1,%2,%3};"
        : "+f"(d[0]), "+f"(d[1]), "+f"(d[2]), "+f"(d[3])
        : "r"(a[0]), "r"(a[1]), "r"(a[2]), "r"(a[3]), "r"(b0), "r"(b1));
}

// ---- prologue: build fragment-order B (one tiny block) ---------------------
__global__ void build_Bfrag(const float* __restrict__ attn1_W,
                            const float* __restrict__ attn1_b) {
    for (int t = threadIdx.x; t < 5 * 4 * 2 * 32; t += blockDim.x) {
        int l   = t & 31;
        int r   = (t >> 5) & 1;
        int nn  = (t >> 6) & 3;
        int kk  = t >> 8;
        int n   = 8 * nn + (l >> 2);
        int k0  = 16 * kk + 8 * r + 2 * (l & 3);
        auto bval = [&](int k) -> float {
            if (k < 66)  return attn1_W[k * 32 + n];
            if (k == 66) return attn1_b[n];
            return 0.f;
        };
        g_Bfrag[t] = cvt2bf(bval(k0 + 1), bval(k0));
    }
}

// ---------------------------------------------------------------------------
// One block per batch row. 7 warps; warp w owns positions [32w, 32w+32).
// Warps fully independent until the final 56B reduction.
//
// Gather lane mapping (R8, wavefront-optimal): within each 8-lane row group,
// lane c loads fp32 chunk c of BOTH table rows (full 128B line per LDG.128
// per group), multiplies by the matching target chunk, converts, and stores
// two 8B bf16 pieces into the SW128-swizzled A row. Indices come from
// per-lane registers (idxv/regv, loaded once) via __shfl.
//
// MMA: D[32, 32] per warp = A[32, 80] x B[80, 32]  (bf16 in, fp32 acc)
// ---------------------------------------------------------------------------
__global__ __launch_bounds__(THREADS, 4)
void nais_kernel(const int*   __restrict__ history,
                 const int*   __restrict__ target,
                 const int*   __restrict__ history_region,
                 const int*   __restrict__ target_region,
                 const float* __restrict__ lat_long,
                 const float* __restrict__ W_hist,
                 const float* __restrict__ W_tgt,
                 const float* __restrict__ W_reg,
                 const float* __restrict__ attn2_W,
                 const float* __restrict__ dist_W,
                 const float* __restrict__ dist_b,
                 float*       __restrict__ out)
{
    __shared__ __align__(16) unsigned char s_A[NWARP * AW_BYTES];
    __shared__ float  s_dot[NWARP * 32];
    __shared__ float2 s_red[NWARP];

    const int b    = blockIdx.x;
    const int tid  = threadIdx.x;
    const int w    = tid >> 5;
    const int lane = tid & 31;
    const int gid  = lane >> 2;
    const int tig  = lane & 3;
    const int base = b * HH;
    const int tgt  = target[b];
    const int treg = target_region[b];
    const int tb   = 32 * w;
    const int c    = lane & 7;     // fp32 16B-chunk within the 128B table row

    unsigned char* myA = s_A + w * AW_BYTES;

    // ---- per-lane position indices (ONE coalesced load each; shfl later)
    const int posl = min(tb + lane, HH - 1);
    const int idxv = history[base + posl];
    const int regv = history_region[base + posl];

    // ---- this lane's target-embedding chunk (uniform per c; L2/L1 hot)
    const float4 th = *(const float4*)(W_tgt + (size_t)tgt * 32 + 4 * c);
    const float4 tr = *(const float4*)(W_reg + (size_t)treg * 32 + 4 * c);

    // ---- tile1 init: row = lane. chunk0 = (dist placeholder, k66=1.0, 0, 0)
    {
        uint4* r = (uint4*)(myA + T0_BYTES + lane * 32);
        r[0] = make_uint4(0u, 0x00003F80u, 0u, 0u);
        r[1] = make_uint4(0u, 0u, 0u, 0u);
    }

    // ---- dist features -> tile1 word0 (same lane, program-ordered after init)
    {
        float2 ll = *(const float2*)(lat_long + (size_t)(base + posl) * 2);
        const float dw00 = dist_W[0] * 100.f, dw01 = dist_W[1] * 100.f;
        const float dw10 = dist_W[2] * 100.f, dw11 = dist_W[3] * 100.f;
        float d0 = sigm(fmaf(ll.x, dw00, fmaf(ll.y, dw10, dist_b[0])));
        float d1 = sigm(fmaf(ll.x, dw01, fmaf(ll.y, dw11, dist_b[1])));
        *(uint32_t*)(myA + T0_BYTES + lane * 32) = cvt2bf(d1, d0);
    }

    // ---- gather + product + fp32 dot + cvt + swizzled store
    {
        const int rsel = lane >> 3;    // which of 4 rows this lane serves per q
#pragma unroll
        for (int q = 0; q < 8; q++) {
            int prow = 4 * q + rsel;   // local position 0..31
            int ii = __shfl_sync(0xffffffffu, idxv, prow);
            int rr = __shfl_sync(0xffffffffu, regv, prow);
            float4 eh = *(const float4*)(W_hist + (size_t)ii * 32 + 4 * c);
            float4 er = *(const float4*)(W_reg  + (size_t)rr * 32 + 4 * c);
            float ph0 = eh.x * th.x, ph1 = eh.y * th.y;
            float ph2 = eh.z * th.z, ph3 = eh.w * th.w;
            float pr0 = er.x * tr.x, pr1 = er.y * tr.y;
            float pr2 = er.z * tr.z, pr3 = er.w * tr.w;
            uint2 hv = make_uint2(cvt2bf(ph1, ph0), cvt2bf(ph3, ph2));
            uint2 rv = make_uint2(cvt2bf(pr1, pr0), cvt2bf(pr3, pr2));
            // bf16 dest: hist -> 16B-chunks 0..3, reg -> 4..7 (SW128 xor row&7)
            uint32_t half8 = (c & 1) << 3;
            uint32_t a0 = prow * 128 + ((((c >> 1)    ) ^ (prow & 7)) << 4) + half8;
            uint32_t a1 = prow * 128 + ((((c >> 1) + 4) ^ (prow & 7)) << 4) + half8;
            *(uint2*)(myA + a0) = hv;
            *(uint2*)(myA + a1) = rv;
            // fp32 dot over the 8 lanes sharing this row
            float part = ((ph0 + ph1) + (ph2 + ph3)) + ((pr0 + pr1) + (pr2 + pr3));
            part += __shfl_xor_sync(0xffffffffu, part, 1);
            part += __shfl_xor_sync(0xffffffffu, part, 2);
            part += __shfl_xor_sync(0xffffffffu, part, 4);
            if (c == 0) s_dot[w * 32 + prow] = part;
        }
    }
    __syncwarp();   // per-warp only: A tile + s_dot visible to this warp

    // ---- MMA: 2 m-tiles x 4 n-tiles x 5 k-steps; B frags via LDG
    float d[2][4][4];
#pragma unroll
    for (int mt = 0; mt < 2; mt++)
#pragma unroll
        for (int nn = 0; nn < 4; nn++)
#pragma unroll
            for (int i = 0; i < 4; i++) d[mt][nn][i] = 0.f;

    const uint32_t aT0 = (uint32_t)__cvta_generic_to_shared(myA);
    const uint32_t aT1 = aT0 + T0_BYTES;

#pragma unroll
    for (int kk = 0; kk < 5; kk++) {
        uint32_t a[2][4];
#pragma unroll
        for (int mt = 0; mt < 2; mt++) {
            int row = 16 * mt + (lane & 15);
            uint32_t addr;
            if (kk < 4) {
                int chunk = 2 * kk + (lane >> 4);
                addr = aT0 + row * 128 + ((chunk ^ (row & 7)) << 4);
            } else {
                addr = aT1 + row * 32 + ((lane >> 4) << 4);
            }
            ldsm_x4(addr, a[mt][0], a[mt][1], a[mt][2], a[mt][3]);
        }
#pragma unroll
        for (int nn = 0; nn < 4; nn++) {
            uint32_t b0 = g_Bfrag[((kk * 4 + nn) * 2    ) * 32 + lane];
            uint32_t b1 = g_Bfrag[((kk * 4 + nn) * 2 + 1) * 32 + lane];
            mma16816(d[0][nn], a[0], b0, b1);
            mma16816(d[1][nn], a[1], b0, b1);
        }
    }

    // ---- epilogue: relu(hid) . w2, masked exp, reduce
    float v00 = 0.f, v01 = 0.f, v10 = 0.f, v11 = 0.f;
#pragma unroll
    for (int nn = 0; nn < 4; nn++) {
        float2 w2 = *(const float2*)(attn2_W + 8 * nn + 2 * tig);
        v00 = fmaf(fmaxf(d[0][nn][0], 0.f), w2.x, fmaf(fmaxf(d[0][nn][1], 0.f), w2.y, v00));
        v01 = fmaf(fmaxf(d[0][nn][2], 0.f), w2.x, fmaf(fmaxf(d[0][nn][3], 0.f), w2.y, v01));
        v10 = fmaf(fmaxf(d[1][nn][0], 0.f), w2.x, fmaf(fmaxf(d[1][nn][1], 0.f), w2.y, v10));
        v11 = fmaf(fmaxf(d[1][nn][2], 0.f), w2.x, fmaf(fmaxf(d[1][nn][3], 0.f), w2.y, v11));
    }
#pragma unroll
    for (int off = 1; off <= 2; off <<= 1) {
        v00 += __shfl_xor_sync(0xffffffffu, v00, off);
        v01 += __shfl_xor_sync(0xffffffffu, v01, off);
        v10 += __shfl_xor_sync(0xffffffffu, v10, off);
        v11 += __shfl_xor_sync(0xffffffffu, v11, off);
    }
    float score = (tig == 0) ? v00 : (tig == 1) ? v01 : (tig == 2) ? v10 : v11;

    int posl2 = gid + 8 * tig;                       // local row this lane owns
    float dotv = s_dot[w * 32 + posl2];              // fp32 dot (conflict-free)
    int idx = __shfl_sync(0xffffffffu, idxv, posl2); // no reload
    bool ok = (idx != tgt) && (tb + posl2 < HH);
    float e  = ok ? __expf(score) : 0.f;
    float se = e;
    float sp = e * dotv;
#pragma unroll
    for (int off = 16; off; off >>= 1) {
        se += __shfl_xor_sync(0xffffffffu, se, off);
        sp += __shfl_xor_sync(0xffffffffu, sp, off);
    }
    if (lane == 0) s_red[w] = make_float2(se, sp);
    __syncthreads();
    if (tid == 0) {
        float SE = 0.f, SP = 0.f;
#pragma unroll
        for (int i = 0; i < NWARP; i++) { SE += s_red[i].x; SP += s_red[i].y; }
        out[b] = sigm(SP * rsqrtf(SE));   // BETA=0.5: pred = SP / sqrt(SE)
    }
}

extern "C" void kernel_launch(void* const* d_in, const int* in_sizes, int n_in,
                              void* d_out, int out_size) {
    const int B = in_sizes[1];   // target is [B]
    build_Bfrag<<<1, 256>>>((const float*)d_in[8], (const float*)d_in[9]);
    nais_kernel<<<B, THREADS>>>(
        (const int*)  d_in[0],   // history [B,H]
        (const int*)  d_in[1],   // target [B]
        (const int*)  d_in[2],   // history_region [B,H]
        (const int*)  d_in[3],   // target_region [B]
        (const float*)d_in[4],   // target_lat_long [B,H,2]
        (const float*)d_in[5],   // W_hist
        (const float*)d_in[6],   // W_tgt
        (const float*)d_in[7],   // W_reg
        (const float*)d_in[10],  // attn2_W [32,1]
        (const float*)d_in[11],  // dist_W [2,2]
        (const float*)d_in[12],  // dist_b [2]
        (float*)d_out);
}